// round 1
// baseline (speedup 1.0000x reference)
#include <cuda_runtime.h>
#include <math.h>

// Problem constants: x [8,256,128,128] f32, params [8,512] f32, W [256,512] f32
#define Bn   8
#define Cn   256
#define HWn  16384          // 128*128
#define CHWn (Cn * HWn)     // 4194304
#define EPSf 1e-5f

// ---------------- device scratch (no allocations allowed) ----------------
__device__ float g_sum  [Bn * Cn];
__device__ float g_sumsq[Bn * Cn];
__device__ float g_mean [Bn * Cn];
__device__ float g_rstd [Bn * Cn];
__device__ float g_Mb[Bn];
__device__ float g_Rb[Bn];
__device__ float g_G[Bn * Cn * Cn];   // per-batch effective weight [b][o][c], 2 MB
__device__ float g_e[Bn * Cn];        // per-batch bias per output channel

// ---------------- helpers ----------------
__device__ __forceinline__ float warp_sum(float v) {
#pragma unroll
    for (int off = 16; off > 0; off >>= 1)
        v += __shfl_down_sync(0xffffffffu, v, off);
    return v;
}

// ---------------- kernel 1: per-(b,c) stats ----------------
__global__ __launch_bounds__(256) void k_stats_bc(const float* __restrict__ x) {
    const int bc = blockIdx.x;                 // 0..2047
    const float4* p = reinterpret_cast<const float4*>(x + (size_t)bc * HWn);
    float s = 0.f, ss = 0.f;
#pragma unroll 4
    for (int i = threadIdx.x; i < HWn / 4; i += 256) {
        float4 v = p[i];
        s  += v.x + v.y + v.z + v.w;
        ss += v.x * v.x + v.y * v.y + v.z * v.z + v.w * v.w;
    }
    __shared__ float sb_s[8], sb_q[8];
    float ws = warp_sum(s), wq = warp_sum(ss);
    int lane = threadIdx.x & 31, w = threadIdx.x >> 5;
    if (lane == 0) { sb_s[w] = ws; sb_q[w] = wq; }
    __syncthreads();
    if (w == 0) {
        float ts = (lane < 8) ? sb_s[lane] : 0.f;
        float tq = (lane < 8) ? sb_q[lane] : 0.f;
#pragma unroll
        for (int off = 4; off > 0; off >>= 1) {
            ts += __shfl_down_sync(0xffu, ts, off);
            tq += __shfl_down_sync(0xffu, tq, off);
        }
        if (lane == 0) {
            g_sum[bc]   = ts;
            g_sumsq[bc] = tq;
            float mean = ts * (1.0f / HWn);
            float var  = tq * (1.0f / HWn) - mean * mean;
            g_mean[bc] = mean;
            g_rstd[bc] = rsqrtf(var + EPSf);
        }
    }
}

// ---------------- kernel 2: per-batch LN stats ----------------
__global__ __launch_bounds__(256) void k_stats_b() {
    const int b = blockIdx.x;
    float s  = g_sum  [b * Cn + threadIdx.x];
    float ss = g_sumsq[b * Cn + threadIdx.x];
    __shared__ float sb_s[8], sb_q[8];
    float ws = warp_sum(s), wq = warp_sum(ss);
    int lane = threadIdx.x & 31, w = threadIdx.x >> 5;
    if (lane == 0) { sb_s[w] = ws; sb_q[w] = wq; }
    __syncthreads();
    if (w == 0) {
        float ts = (lane < 8) ? sb_s[lane] : 0.f;
        float tq = (lane < 8) ? sb_q[lane] : 0.f;
#pragma unroll
        for (int off = 4; off > 0; off >>= 1) {
            ts += __shfl_down_sync(0xffu, ts, off);
            tq += __shfl_down_sync(0xffu, tq, off);
        }
        if (lane == 0) {
            float M   = ts * (1.0f / CHWn);
            float var = tq * (1.0f / CHWn) - M * M;
            g_Mb[b] = M;
            g_Rb[b] = rsqrtf(var + EPSf);
        }
    }
}

// ---------------- kernel 3: build effective weight G and bias e ----------------
// out[b,o,hw] = sum_c G[b,o,c] * x[b,c,hw] + e[b,o]
// G[b,o,c] = gamma[b,o] * (W1[o,c]*r_bc + R_b*W2[o,c])
// e[b,o]   = beta[b,o] - gamma[b,o] * sum_c (W1[o,c]*r_bc*m_bc + R_b*M_b*W2[o,c])
__global__ __launch_bounds__(256) void k_build_G(const float* __restrict__ params,
                                                 const float* __restrict__ W) {
    const int o = blockIdx.x;       // output channel
    const int b = blockIdx.y;       // batch
    const int c = threadIdx.x;      // input channel
    float r  = g_rstd[b * Cn + c];
    float m  = g_mean[b * Cn + c];
    float Rb = g_Rb[b];
    float Mb = g_Mb[b];
    float w1 = W[o * (2 * Cn) + c];
    float w2 = W[o * (2 * Cn) + Cn + c];
    float gamma = params[b * (2 * Cn) + o];
    float a     = w1 * r + Rb * w2;
    float dpart = w1 * r * m + Rb * Mb * w2;
    g_G[((size_t)b * Cn + o) * Cn + c] = gamma * a;

    __shared__ float sb[8];
    float wd = warp_sum(dpart);
    int lane = threadIdx.x & 31, w = threadIdx.x >> 5;
    if (lane == 0) sb[w] = wd;
    __syncthreads();
    if (w == 0) {
        float td = (lane < 8) ? sb[lane] : 0.f;
#pragma unroll
        for (int off = 4; off > 0; off >>= 1)
            td += __shfl_down_sync(0xffu, td, off);
        if (lane == 0) {
            float beta = params[b * (2 * Cn) + Cn + o];
            g_e[b * Cn + o] = beta - gamma * td;
        }
    }
}

// ---------------- kernel 4: batched GEMM + bias ----------------
// Per batch b:  C[256, 16384] = G[b](256x256) @ X[b](256x16384) + e[b]
// Tile: BM=128, BN=128, BK=16. 256 threads, 8x8 accumulators each.
#define BM 128
#define BN 128
#define BK 16

__global__ __launch_bounds__(256) void k_gemm(const float* __restrict__ x,
                                              float* __restrict__ out) {
    const int b  = blockIdx.z;
    const int by = blockIdx.y;          // 0..1   (row tile)
    const int bx = blockIdx.x;          // 0..127 (col tile over HW)
    const float* A  = g_G + (size_t)b * Cn * Cn;
    const float* Bm = x   + (size_t)b * CHWn;
    float*       Cm = out + (size_t)b * CHWn;

    __shared__ float As[BK][BM];        // transposed A tile
    __shared__ float Bs[BK][BN];

    const int tid = threadIdx.x;
    const int ty  = tid >> 4;           // 0..15
    const int tx  = tid & 15;           // 0..15

    // A-tile load mapping: row = tid>>1 (0..127), col group = (tid&1)*8
    const int a_row = tid >> 1;
    const int a_col = (tid & 1) * 8;
    // B-tile load mapping: row = tid>>4 (0..15), col = (tid&15)*8
    const int b_row = tid >> 4;
    const int b_col = (tid & 15) * 8;

    const float* Aptr = A  + (by * BM + a_row) * Cn + a_col;
    const float* Bptr = Bm + b_row * HWn + bx * BN + b_col;

    float acc[8][8];
#pragma unroll
    for (int i = 0; i < 8; i++)
#pragma unroll
        for (int j = 0; j < 8; j++) acc[i][j] = 0.f;

    // prologue: fetch tile 0 into registers
    float4 ra0 = *reinterpret_cast<const float4*>(Aptr);
    float4 ra1 = *reinterpret_cast<const float4*>(Aptr + 4);
    float4 rb0 = *reinterpret_cast<const float4*>(Bptr);
    float4 rb1 = *reinterpret_cast<const float4*>(Bptr + 4);

    const int NK = Cn / BK;             // 16
    for (int kt = 0; kt < NK; kt++) {
        __syncthreads();                // prev compute done, safe to overwrite smem
        // store A transposed
        As[a_col + 0][a_row] = ra0.x;
        As[a_col + 1][a_row] = ra0.y;
        As[a_col + 2][a_row] = ra0.z;
        As[a_col + 3][a_row] = ra0.w;
        As[a_col + 4][a_row] = ra1.x;
        As[a_col + 5][a_row] = ra1.y;
        As[a_col + 6][a_row] = ra1.z;
        As[a_col + 7][a_row] = ra1.w;
        *reinterpret_cast<float4*>(&Bs[b_row][b_col])     = rb0;
        *reinterpret_cast<float4*>(&Bs[b_row][b_col + 4]) = rb1;
        __syncthreads();

        // prefetch next tile while computing this one
        if (kt + 1 < NK) {
            const float* An = Aptr + (kt + 1) * BK;
            const float* Bp = Bptr + (kt + 1) * BK * HWn;
            ra0 = *reinterpret_cast<const float4*>(An);
            ra1 = *reinterpret_cast<const float4*>(An + 4);
            rb0 = *reinterpret_cast<const float4*>(Bp);
            rb1 = *reinterpret_cast<const float4*>(Bp + 4);
        }

#pragma unroll
        for (int kk = 0; kk < BK; kk++) {
            float ar[8], br[8];
            *reinterpret_cast<float4*>(&ar[0]) = *reinterpret_cast<const float4*>(&As[kk][ty * 4]);
            *reinterpret_cast<float4*>(&ar[4]) = *reinterpret_cast<const float4*>(&As[kk][64 + ty * 4]);
            *reinterpret_cast<float4*>(&br[0]) = *reinterpret_cast<const float4*>(&Bs[kk][tx * 4]);
            *reinterpret_cast<float4*>(&br[4]) = *reinterpret_cast<const float4*>(&Bs[kk][64 + tx * 4]);
#pragma unroll
            for (int i = 0; i < 8; i++)
#pragma unroll
                for (int j = 0; j < 8; j++)
                    acc[i][j] += ar[i] * br[j];
        }
    }

    // epilogue: add bias, store
#pragma unroll
    for (int rg = 0; rg < 2; rg++) {
#pragma unroll
        for (int ii = 0; ii < 4; ii++) {
            int row = by * BM + rg * 64 + ty * 4 + ii;
            float eb = g_e[b * Cn + row];
            float* crow = Cm + (size_t)row * HWn + bx * BN;
#pragma unroll
            for (int cg = 0; cg < 2; cg++) {
                float4 v;
                v.x = acc[rg * 4 + ii][cg * 4 + 0] + eb;
                v.y = acc[rg * 4 + ii][cg * 4 + 1] + eb;
                v.z = acc[rg * 4 + ii][cg * 4 + 2] + eb;
                v.w = acc[rg * 4 + ii][cg * 4 + 3] + eb;
                *reinterpret_cast<float4*>(crow + cg * 64 + tx * 4) = v;
            }
        }
    }
}

// ---------------- launch ----------------
extern "C" void kernel_launch(void* const* d_in, const int* in_sizes, int n_in,
                              void* d_out, int out_size) {
    const float* x      = (const float*)d_in[0];   // [8,256,128,128]
    const float* params = (const float*)d_in[1];   // [8,512]
    const float* W      = (const float*)d_in[2];   // [256,512]
    float* out          = (float*)d_out;

    k_stats_bc<<<Bn * Cn, 256>>>(x);
    k_stats_b<<<Bn, 256>>>();
    k_build_G<<<dim3(Cn, Bn), 256>>>(params, W);
    k_gemm<<<dim3(HWn / BN, Cn / BM, Bn), 256>>>(x, out);
}

// round 3
// speedup vs baseline: 2.6362x; 2.6362x over previous
#include <cuda_runtime.h>
#include <math.h>

// Problem constants: x [8,256,128,128] f32, params [8,512] f32, W [256,512] f32
#define Bn   8
#define Cn   256
#define HWn  16384          // 128*128
#define CHWn (Cn * HWn)     // 4194304
#define EPSf 1e-5f

// ---------------- device scratch ----------------
__device__ float g_sum  [Bn * Cn];
__device__ float g_sumsq[Bn * Cn];
__device__ float g_mean [Bn * Cn];
__device__ float g_rstd [Bn * Cn];
__device__ float g_Mb[Bn];
__device__ float g_Rb[Bn];
// G packed in mma fragment order: [b][kt(8)][mtblk(2)][s(4)][mtl(8)][lane(32)][j(4)]
__device__ float g_Gp[Bn * Cn * Cn];
__device__ float g_e[Bn * Cn];

__device__ __forceinline__ float warp_sum(float v) {
#pragma unroll
    for (int off = 16; off > 0; off >>= 1)
        v += __shfl_down_sync(0xffffffffu, v, off);
    return v;
}

// ---------------- kernel 1: per-(b,c) stats ----------------
__global__ __launch_bounds__(256) void k_stats_bc(const float* __restrict__ x) {
    const int bc = blockIdx.x;
    const float4* p = reinterpret_cast<const float4*>(x + (size_t)bc * HWn);
    float s = 0.f, ss = 0.f;
#pragma unroll 4
    for (int i = threadIdx.x; i < HWn / 4; i += 256) {
        float4 v = p[i];
        s  += v.x + v.y + v.z + v.w;
        ss += v.x * v.x + v.y * v.y + v.z * v.z + v.w * v.w;
    }
    __shared__ float sb_s[8], sb_q[8];
    float ws = warp_sum(s), wq = warp_sum(ss);
    int lane = threadIdx.x & 31, w = threadIdx.x >> 5;
    if (lane == 0) { sb_s[w] = ws; sb_q[w] = wq; }
    __syncthreads();
    if (w == 0) {
        float ts = (lane < 8) ? sb_s[lane] : 0.f;
        float tq = (lane < 8) ? sb_q[lane] : 0.f;
#pragma unroll
        for (int off = 4; off > 0; off >>= 1) {
            ts += __shfl_down_sync(0xffu, ts, off);
            tq += __shfl_down_sync(0xffu, tq, off);
        }
        if (lane == 0) {
            g_sum[bc]   = ts;
            g_sumsq[bc] = tq;
            float mean = ts * (1.0f / HWn);
            float var  = tq * (1.0f / HWn) - mean * mean;
            g_mean[bc] = mean;
            g_rstd[bc] = rsqrtf(var + EPSf);
        }
    }
}

// ---------------- kernel 2: per-batch LN stats ----------------
__global__ __launch_bounds__(256) void k_stats_b() {
    const int b = blockIdx.x;
    float s  = g_sum  [b * Cn + threadIdx.x];
    float ss = g_sumsq[b * Cn + threadIdx.x];
    __shared__ float sb_s[8], sb_q[8];
    float ws = warp_sum(s), wq = warp_sum(ss);
    int lane = threadIdx.x & 31, w = threadIdx.x >> 5;
    if (lane == 0) { sb_s[w] = ws; sb_q[w] = wq; }
    __syncthreads();
    if (w == 0) {
        float ts = (lane < 8) ? sb_s[lane] : 0.f;
        float tq = (lane < 8) ? sb_q[lane] : 0.f;
#pragma unroll
        for (int off = 4; off > 0; off >>= 1) {
            ts += __shfl_down_sync(0xffu, ts, off);
            tq += __shfl_down_sync(0xffu, tq, off);
        }
        if (lane == 0) {
            float M   = ts * (1.0f / CHWn);
            float var = tq * (1.0f / CHWn) - M * M;
            g_Mb[b] = M;
            g_Rb[b] = rsqrtf(var + EPSf);
        }
    }
}

// ---------------- kernel 3: build packed tf32 G and bias e ----------------
// G[b,o,c] = gamma[b,o]*(W1[o,c]*r_bc + R_b*W2[o,c])
// e[b,o]   = beta[b,o] - gamma[b,o]*sum_c(W1[o,c]*r_bc*m_bc + R_b*M_b*W2[o,c])
__global__ __launch_bounds__(256) void k_build_G(const float* __restrict__ params,
                                                 const float* __restrict__ W) {
    const int o = blockIdx.x;
    const int b = blockIdx.y;
    const int c = threadIdx.x;
    float r  = g_rstd[b * Cn + c];
    float m  = g_mean[b * Cn + c];
    float Rb = g_Rb[b];
    float Mb = g_Mb[b];
    float w1 = W[o * (2 * Cn) + c];
    float w2 = W[o * (2 * Cn) + Cn + c];
    float gamma = params[b * (2 * Cn) + o];
    float a     = w1 * r + Rb * w2;
    float dpart = w1 * r * m + Rb * Mb * w2;
    float val   = gamma * a;

    // pre-round to tf32 (rna) and scatter into fragment order
    unsigned tv;
    asm("cvt.rna.tf32.f32 %0, %1;" : "=r"(tv) : "f"(val));
    int kt = c >> 5, s = (c >> 3) & 3, t = c & 3, cbit = (c >> 2) & 1;
    int mtblk = o >> 7, mtl = (o >> 4) & 7, rbit = (o >> 3) & 1, g = o & 7;
    int lane = g * 4 + t;
    int j = rbit + 2 * cbit;
    size_t idx = (((((size_t)(b * 8 + kt) * 2 + mtblk) * 4 + s) * 8 + mtl) * 32 + lane) * 4 + j;
    reinterpret_cast<unsigned*>(g_Gp)[idx] = tv;

    __shared__ float sb[8];
    float wd = warp_sum(dpart);
    int ln = threadIdx.x & 31, w = threadIdx.x >> 5;
    if (ln == 0) sb[w] = wd;
    __syncthreads();
    if (w == 0) {
        float td = (ln < 8) ? sb[ln] : 0.f;
#pragma unroll
        for (int off = 4; off > 0; off >>= 1)
            td += __shfl_down_sync(0xffu, td, off);
        if (ln == 0) {
            float beta = params[b * (2 * Cn) + Cn + o];
            g_e[b * Cn + o] = beta - gamma * td;
        }
    }
}

// ---------------- kernel 4: TF32 tensor-core GEMM + bias ----------------
// Per batch: C[256,16384] = G[256,256] @ X[256,16384] + e
// CTA tile 128x128, BK=32, 8 warps (2x4), warp tile 64x32, mma m16n8k8.
#define BSTRIDE 136   // Bs row stride in floats: bank = (8t+g)%32, conflict-free
#define A_TILE_F 4096             // 128x32 floats (fragment-packed)
#define B_TILE_F (32 * BSTRIDE)   // 4352 floats
#define SMEM_FLOATS (2 * A_TILE_F + 2 * B_TILE_F)   // 16896 floats = 67584 B

__global__ __launch_bounds__(256) void k_gemm(const float* __restrict__ x,
                                              float* __restrict__ out) {
    extern __shared__ float smem[];
    const int b  = blockIdx.z;
    const int by = blockIdx.y;
    const int bx = blockIdx.x;
    const int tid  = threadIdx.x;
    const int lane = tid & 31;
    const int wid  = tid >> 5;
    const int wr = wid >> 2;     // 0..1 (row band of 64)
    const int wc = wid & 3;      // 0..3 (col band of 32)
    const int g  = lane >> 2;    // 0..7
    const int t  = lane & 3;     // 0..3

    const unsigned smem_u = (unsigned)__cvta_generic_to_shared(smem);
    const float* gB0 = x + (size_t)b * CHWn + bx * 128;
    const int br = tid >> 3;           // B load: row 0..31
    const int bq = tid & 7;            // B load: float4 lane 0..7

    float acc[4][4][4];
#pragma unroll
    for (int mi = 0; mi < 4; mi++)
#pragma unroll
        for (int ni = 0; ni < 4; ni++)
#pragma unroll
            for (int k = 0; k < 4; k++) acc[mi][ni][k] = 0.f;

#define LOAD_TILES(KT, BUF)                                                          \
    {                                                                                \
        const float* asrc = g_Gp + (((size_t)(b * 8 + (KT)) * 2 + by) * A_TILE_F);   \
        unsigned adst = smem_u + (BUF) * A_TILE_F * 4;                               \
        _Pragma("unroll")                                                            \
        for (int i = 0; i < 4; i++) {                                                \
            int f = tid + i * 256;                                                   \
            asm volatile("cp.async.cg.shared.global [%0], [%1], 16;" ::              \
                         "r"(adst + f * 16), "l"(asrc + f * 4));                     \
        }                                                                            \
        const float* brow = gB0 + (size_t)((KT) * 32 + br) * HWn;                    \
        unsigned bdst = smem_u + (2 * A_TILE_F + (BUF) * B_TILE_F + br * BSTRIDE) * 4;\
        _Pragma("unroll")                                                            \
        for (int i = 0; i < 4; i++) {                                                \
            int q = bq + i * 8;                                                      \
            asm volatile("cp.async.cg.shared.global [%0], [%1], 16;" ::              \
                         "r"(bdst + q * 16), "l"(brow + q * 4));                     \
        }                                                                            \
        asm volatile("cp.async.commit_group;");                                      \
    }

    LOAD_TILES(0, 0)
    int buf = 0;

    for (int kt = 0; kt < 8; kt++) {
        asm volatile("cp.async.wait_group 0;");
        __syncthreads();
        if (kt < 7) LOAD_TILES(kt + 1, buf ^ 1)

        const uint4* Af = reinterpret_cast<const uint4*>(smem + buf * A_TILE_F);
        const float* Bf = smem + 2 * A_TILE_F + buf * B_TILE_F;

#pragma unroll
        for (int s = 0; s < 4; s++) {
            uint4 a[4];
#pragma unroll
            for (int mi = 0; mi < 4; mi++)
                a[mi] = Af[(s * 8 + wr * 4 + mi) * 32 + lane];
            unsigned bf0[4], bf1[4];
#pragma unroll
            for (int ni = 0; ni < 4; ni++) {
                float f0 = Bf[(s * 8 + t) * BSTRIDE + wc * 32 + ni * 8 + g];
                float f1 = Bf[(s * 8 + t + 4) * BSTRIDE + wc * 32 + ni * 8 + g];
                asm("cvt.rna.tf32.f32 %0, %1;" : "=r"(bf0[ni]) : "f"(f0));
                asm("cvt.rna.tf32.f32 %0, %1;" : "=r"(bf1[ni]) : "f"(f1));
            }
#pragma unroll
            for (int mi = 0; mi < 4; mi++)
#pragma unroll
                for (int ni = 0; ni < 4; ni++)
                    asm volatile(
                        "mma.sync.aligned.m16n8k8.row.col.f32.tf32.tf32.f32 "
                        "{%0,%1,%2,%3}, {%4,%5,%6,%7}, {%8,%9}, {%0,%1,%2,%3};"
                        : "+f"(acc[mi][ni][0]), "+f"(acc[mi][ni][1]),
                          "+f"(acc[mi][ni][2]), "+f"(acc[mi][ni][3])
                        : "r"(a[mi].x), "r"(a[mi].y), "r"(a[mi].z), "r"(a[mi].w),
                          "r"(bf0[ni]), "r"(bf1[ni]));
        }
        buf ^= 1;
    }

    // epilogue: bias + store (float2, 32B sectors fully covered)
    float* Cm = out + (size_t)b * CHWn + (size_t)(by * 128) * HWn + bx * 128;
    const float* eb = g_e + b * Cn + by * 128;
#pragma unroll
    for (int mi = 0; mi < 4; mi++) {
        int r0 = wr * 64 + mi * 16 + g;
        float e0 = eb[r0], e1 = eb[r0 + 8];
        float* p0 = Cm + (size_t)r0 * HWn + wc * 32 + 2 * t;
        float* p1 = p0 + (size_t)8 * HWn;
#pragma unroll
        for (int ni = 0; ni < 4; ni++) {
            float2 v0 = make_float2(acc[mi][ni][0] + e0, acc[mi][ni][1] + e0);
            float2 v1 = make_float2(acc[mi][ni][2] + e1, acc[mi][ni][3] + e1);
            *reinterpret_cast<float2*>(p0 + ni * 8) = v0;
            *reinterpret_cast<float2*>(p1 + ni * 8) = v1;
        }
    }
}

// ---------------- launch ----------------
extern "C" void kernel_launch(void* const* d_in, const int* in_sizes, int n_in,
                              void* d_out, int out_size) {
    const float* x      = (const float*)d_in[0];
    const float* params = (const float*)d_in[1];
    const float* W      = (const float*)d_in[2];
    float* out          = (float*)d_out;

    cudaFuncSetAttribute(k_gemm, cudaFuncAttributeMaxDynamicSharedMemorySize,
                         SMEM_FLOATS * 4);

    k_stats_bc<<<Bn * Cn, 256>>>(x);
    k_stats_b<<<Bn, 256>>>();
    k_build_G<<<dim3(Cn, Bn), 256>>>(params, W);
    k_gemm<<<dim3(HWn / 128, Cn / 128, Bn), 256, SMEM_FLOATS * 4>>>(x, out);
}